// round 13
// baseline (speedup 1.0000x reference)
#include <cuda_runtime.h>
#include <cstdint>

// Problem shape (fixed by the reference)
#define T_STEPS 5
#define BB 32
#define CC 128
#define HW 1024
#define NPT (BB * CC * HW)        // 4,194,304 elements per timestep
#define N4  (NPT / 4)             // 1,048,576 float4 per timestep
#define BATCH_F4 (CC * HW / 4)    // 32768 float4 per batch slice
#define NPLANES (BB * CC)         // 4096, ordered c-major: p = c*32 + b

#define NBLK 152                  // one CTA per SM, all resident (smem-forced occ 1)
#define NTHR 1024
#define ITPS 7                    // ceil(27*256/1024) iterations per step
#define KTOT (T_STEPS * ITPS)     // 35 flat iterations
#define SMEM_DYN (120 * 1024)     // >= 6912 float4 carry; pads to force occ=1

static constexpr float V_TH    = 0.5f;
static constexpr float W_DEC   = 0.5f;
static constexpr float LOWER_C = 0.2f - 0.03f;
static constexpr float UPPER_C = 0.2f + 0.03f;
static constexpr float EMA0    = 0.17f;
static constexpr float INV_N   = 1.0f / 32768.0f;

// Cross-CTA state (device globals — no allocation allowed)
__device__ float g_chsum[T_STEPS - 1][CC];   // per-step per-channel spike sums
__device__ int   g_prog[NBLK];               // per-CTA step progress flags

__device__ __forceinline__ float sigmoidf(float x) {
    return 1.0f / (1.0f + expf(-x));
}

__global__ void lif_init() {
    int i = threadIdx.x;
    if (i < (T_STEPS - 1) * CC) ((float*)g_chsum)[i] = 0.0f;
    if (i < NBLK) g_prog[i] = 0;
}

// CTA owning c-major plane p (partition p0(k) = k*512/19; 4096/152 = 512/19)
__device__ __forceinline__ int cta_of(int p) {
    int k = (p * 19) >> 9;                    // lower bound, then fix up
    while (((k + 1) * 512) / 19 <= p) ++k;
    return k;
}

// 152 CTAs, one per SM. Planes partitioned c-major so each CTA touches <=2
// channels and each channel spans 2-3 ADJACENT CTAs. Per-step channel sums
// via global atomics; each CTA spins only on its neighbor CTAs' progress
// flags (no global barrier). Membrane carry in smem; flat 35-iteration
// unrolled stream with 3-slot load ring carried across step boundaries.
__global__ __launch_bounds__(NTHR, 1)
void lif_all(const float* __restrict__ xe,
             const float* __restrict__ xi,
             const float* __restrict__ alpha_raw,
             const float* __restrict__ beta_raw,
             float* __restrict__ out)
{
    extern __shared__ float4 s_mem[];         // carry, indexed by local i
    __shared__ float s_w0[32], s_w1[32];
    __shared__ float s_bw[2];

    const int tid  = threadIdx.x;
    const int lane = tid & 31;
    const int wid  = tid >> 5;
    const int bid  = blockIdx.x;

    const int p0 = (bid * 512) / 19;          // first owned plane (c-major)
    const int p1 = ((bid + 1) * 512) / 19;
    const int count4 = (p1 - p0) * 256;       // owned float4 (6656 or 6912)
    const int c0 = p0 >> 5;                   // first owned channel
    const int c1 = (p1 - 1) >> 5;             // last owned channel (c0 or c0+1)
    const int kA = cta_of(32 * c0);           // neighbor wait range
    const int kB = cta_of(32 * c1 + 31);

    const float alpha = 4.0f * sigmoidf(__ldg(alpha_raw));
    const float beta  = sigmoidf(__ldg(beta_raw));

    const float4* xe4  = reinterpret_cast<const float4*>(xe);
    const float4* xi4  = reinterpret_cast<const float4*>(xi);
    float4*       out4 = reinterpret_cast<float4*>(out);

    float bw0 = beta, bw1 = beta;             // inhw starts at 0
    float cnt0 = 0.0f, cnt1 = 0.0f;

    // Address of local float4 index i at step t (b-major memory layout)
    // pg = p0 + (i>>8); b = pg&31; c = pg>>5; off = i&255
    #define ADDR4(t_, i_) ({                                              \
        const int pg_ = p0 + ((i_) >> 8);                                 \
        (size_t)(t_) * N4 + (size_t)((pg_ & 31) * BATCH_F4                \
            + (pg_ >> 5) * 256 + ((i_) & 255)); })

    float4 er[3], vr[3];
    // Prologue: loads for k=0,1 (t=0)
    {
        const int i0 = tid;                   // always < count4
        const size_t a0 = ADDR4(0, i0);
        er[0] = __ldcs(xe4 + a0);  vr[0] = __ldcs(xi4 + a0);
        const int i1 = 1024 + tid;
        if (i1 < count4) {
            const size_t a1 = ADDR4(0, i1);
            er[1] = __ldcs(xe4 + a1);  vr[1] = __ldcs(xi4 + a1);
        }
    }

    #pragma unroll
    for (int k = 0; k < KTOT; ++k) {
        const int t  = k / ITPS;              // compile-time
        const int it = k % ITPS;

        // Prefetch 2 iterations ahead (crosses step boundaries; inputs
        // don't depend on bw)
        if (k + 2 < KTOT) {
            const int t2  = (k + 2) / ITPS;
            const int i2  = ((k + 2) % ITPS) * 1024 + tid;
            if (i2 < count4) {
                const size_t a2 = ADDR4(t2, i2);
                er[(k + 2) % 3] = __ldcs(xe4 + a2);
                vr[(k + 2) % 3] = __ldcs(xi4 + a2);
            }
        }

        const int i = it * 1024 + tid;
        if (i < count4) {                     // warp-uniform (count4 % 32 == 0)
            const int pg = p0 + (i >> 8);
            const int cl = (pg >> 5) - c0;    // 0 or 1, warp-uniform
            const float bw = cl ? bw1 : bw0;
            const size_t a = ADDR4(t, i);

            const float4 e = er[k % 3];
            const float4 v = vr[k % 3];
            float4 m = (t == 0) ? make_float4(0.f, 0.f, 0.f, 0.f) : s_mem[i];
            float4 s;

            m.x = W_DEC * m.x + e.x / (1.0f + alpha * v.x) - bw * v.x;
            s.x = (m.x >= V_TH) ? 1.0f : 0.0f;  m.x -= V_TH * s.x;
            m.y = W_DEC * m.y + e.y / (1.0f + alpha * v.y) - bw * v.y;
            s.y = (m.y >= V_TH) ? 1.0f : 0.0f;  m.y -= V_TH * s.y;
            m.z = W_DEC * m.z + e.z / (1.0f + alpha * v.z) - bw * v.z;
            s.z = (m.z >= V_TH) ? 1.0f : 0.0f;  m.z -= V_TH * s.z;
            m.w = W_DEC * m.w + e.w / (1.0f + alpha * v.w) - bw * v.w;
            s.w = (m.w >= V_TH) ? 1.0f : 0.0f;  m.w -= V_TH * s.w;

            __stcs(out4 + a, s);
            if (t < T_STEPS - 1) {
                s_mem[i] = m;
                const float sc = s.x + s.y + s.z + s.w;
                cnt0 += cl ? 0.0f : sc;
                cnt1 += cl ? sc : 0.0f;
            }
        }

        // Step boundary: publish channel partials, neighbor-sync, update bw
        if (it == ITPS - 1 && t < T_STEPS - 1) {
            float r0 = cnt0, r1 = cnt1;       // integer-valued: exact any order
            #pragma unroll
            for (int off = 16; off > 0; off >>= 1) {
                r0 += __shfl_down_sync(0xFFFFFFFFu, r0, off);
                r1 += __shfl_down_sync(0xFFFFFFFFu, r1, off);
            }
            if (lane == 0) { s_w0[wid] = r0; s_w1[wid] = r1; }
            __syncthreads();
            if (wid == 0) {
                float x0 = s_w0[lane], x1 = s_w1[lane];   // exactly 32 warps
                #pragma unroll
                for (int off = 16; off > 0; off >>= 1) {
                    x0 += __shfl_down_sync(0xFFFFFFFFu, x0, off);
                    x1 += __shfl_down_sync(0xFFFFFFFFu, x1, off);
                }
                if (lane == 0) {
                    atomicAdd(&g_chsum[t][c0], x0);
                    if (c1 > c0) atomicAdd(&g_chsum[t][c1], x1);
                    __threadfence();
                    atomicExch(&g_prog[bid], t + 1);
                    // Wait only for neighbor contributors of owned channels
                    for (int kk = kA; kk <= kB; ++kk)
                        while (((volatile int*)g_prog)[kk] < t + 1)
                            __nanosleep(64);
                    __threadfence();
                }
            }
            __syncthreads();
            // Rebuild bw for owned channels (EMA recurrence replay)
            if (tid < 2) {
                const int cc = min(c0 + tid, CC - 1);
                float e2 = EMA0;
                for (int kk = 0; kk <= t; ++kk)
                    e2 = 0.9f * e2 + 0.1f * (__ldcg(&g_chsum[kk][cc]) * INV_N);
                const float inhw =
                    4.0f * (sigmoidf(LOWER_C - e2) - sigmoidf(e2 - UPPER_C));
                s_bw[tid] = beta * (1.0f - inhw);
            }
            __syncthreads();
            bw0 = s_bw[0];  bw1 = s_bw[1];
            cnt0 = 0.0f;    cnt1 = 0.0f;
        }
    }
    #undef ADDR4
}

extern "C" void kernel_launch(void* const* d_in, const int* in_sizes, int n_in,
                              void* d_out, int out_size)
{
    const float* xe = (const float*)d_in[0];  // x_exc  [T,B,C,H,W]
    const float* xi = (const float*)d_in[1];  // x_inh  [T,B,C,H,W]
    const float* ar = (const float*)d_in[2];  // alpha_raw scalar
    const float* br = (const float*)d_in[3];  // beta_raw scalar
    float* out = (float*)d_out;               // spikes [T,B,C,H,W]

    static bool attr_set = false;
    if (!attr_set) {
        cudaFuncSetAttribute(lif_all, cudaFuncAttributeMaxDynamicSharedMemorySize,
                             SMEM_DYN);
        attr_set = true;
    }
    lif_init<<<1, (T_STEPS - 1) * CC>>>();
    lif_all<<<NBLK, NTHR, SMEM_DYN>>>(xe, xi, ar, br, out);
}

// round 14
// speedup vs baseline: 1.1870x; 1.1870x over previous
#include <cuda_runtime.h>
#include <cstdint>

// Problem shape (fixed by the reference)
#define T_STEPS 5
#define BB 32
#define CC 128
#define HW 1024                    // 32*32
#define NPT (BB * CC * HW)         // 4,194,304 elements per timestep
#define N4  (NPT / 4)              // 1,048,576 float4 per timestep
#define NTHR 512                   // threads per CTA (one CTA per channel)
#define NWARP (NTHR / 32)          // 16
#define BATCH_F4 (CC * HW / 4)     // 32768 float4 per batch slice
#define KTOT (T_STEPS * 8)         // 40 flat iterations (8 per step)

static constexpr float V_TH    = 0.5f;
static constexpr float W_DEC   = 0.5f;
static constexpr float LOWER_C = 0.2f - 0.03f;   // 0.17
static constexpr float UPPER_C = 0.2f + 0.03f;   // 0.23
static constexpr float EMA0    = 0.17f;
static constexpr float INV_N   = 1.0f / 32768.0f; // 1/(B*H*W)

__device__ __forceinline__ float sigmoidf(float x) {
    return 1.0f / (1.0f + expf(-x));
}

// LIF update for one float4; returns spike vec, updates m in place, accumulates cnt.
__device__ __forceinline__ float4 lif4(float4& m, const float4 e, const float4 v,
                                       const float alpha, const float bw, float& cnt) {
    float4 s;
    m.x = W_DEC * m.x + e.x / (1.0f + alpha * v.x) - bw * v.x;
    s.x = (m.x >= V_TH) ? 1.0f : 0.0f;  m.x -= V_TH * s.x;
    m.y = W_DEC * m.y + e.y / (1.0f + alpha * v.y) - bw * v.y;
    s.y = (m.y >= V_TH) ? 1.0f : 0.0f;  m.y -= V_TH * s.y;
    m.z = W_DEC * m.z + e.z / (1.0f + alpha * v.z) - bw * v.z;
    s.z = (m.z >= V_TH) ? 1.0f : 0.0f;  m.z -= V_TH * s.z;
    m.w = W_DEC * m.w + e.w / (1.0f + alpha * v.w) - bw * v.w;
    s.w = (m.w >= V_TH) ? 1.0f : 0.0f;  m.w -= V_TH * s.w;
    cnt += s.x + s.y + s.z + s.w;
    return s;
}

// One CTA per channel (128 CTAs, each on its own SM). Whole recurrence is
// channel-local. 512 threads; each thread owns 64 elements -> membrane carry
// is 16 float4 in REGISTERS (no smem LDS/STS in the hot loop). Inputs stream
// through a 2-slot register ring (distance-1 prefetch) over a flat, fully
// unrolled 40-iteration stream that crosses step boundaries, so the EMA
// reduction window always has next-step loads in flight.
__global__ __launch_bounds__(NTHR, 1)
void lif_all(const float* __restrict__ xe,
             const float* __restrict__ xi,
             const float* __restrict__ alpha_raw,
             const float* __restrict__ beta_raw,
             float* __restrict__ out)
{
    __shared__ float s_wsum[NWARP];
    __shared__ float s_bw;

    const int c    = blockIdx.x;               // channel
    const int tid  = threadIdx.x;
    const int lane = tid & 31;
    const int wid  = tid >> 5;

    const float alpha = 4.0f * sigmoidf(__ldg(alpha_raw));
    const float beta  = sigmoidf(__ldg(beta_raw));

    // Thread base: batch (tid>>8)∈{0,1}, channel c, offset tid&255.
    // Iteration (t, j) element r∈{0,1}: addr = base + t*N4 + j*4*BATCH_F4 + r*2*BATCH_F4
    const int base4 = (tid >> 8) * BATCH_F4 + c * (HW / 4) + (tid & 255);

    const float4* xe4  = reinterpret_cast<const float4*>(xe)  + base4;
    const float4* xi4  = reinterpret_cast<const float4*>(xi)  + base4;
    float4*       out4 = reinterpret_cast<float4*>(out)       + base4;

    float4 mc[16];                             // membrane carry (registers)
    float4 er[2][2], vr[2][2];                 // 2-slot input ring

    float ema = EMA0;                          // maintained by (wid0,lane0) only
    float bw  = beta;                          // inhw starts at 0
    float cnt = 0.0f;

    // Prologue: loads for k=0
    er[0][0] = __ldcs(xe4);
    er[0][1] = __ldcs(xe4 + 2 * BATCH_F4);
    vr[0][0] = __ldcs(xi4);
    vr[0][1] = __ldcs(xi4 + 2 * BATCH_F4);

    #pragma unroll
    for (int k = 0; k < KTOT; ++k) {
        const int t = k >> 3;                  // step (compile-time)
        const int j = k & 7;                   // chunk within step
        const int s = k & 1;                   // ring slot

        // Prefetch next iteration (crosses step boundaries; inputs are
        // independent of bw)
        if (k + 1 < KTOT) {
            const int t1 = (k + 1) >> 3, j1 = (k + 1) & 7;
            const size_t o1 = (size_t)t1 * N4 + (size_t)j1 * 4 * BATCH_F4;
            er[s ^ 1][0] = __ldcs(xe4 + o1);
            er[s ^ 1][1] = __ldcs(xe4 + o1 + 2 * BATCH_F4);
            vr[s ^ 1][0] = __ldcs(xi4 + o1);
            vr[s ^ 1][1] = __ldcs(xi4 + o1 + 2 * BATCH_F4);
        }

        if (t == 0) { mc[2*j]   = make_float4(0.f, 0.f, 0.f, 0.f);
                      mc[2*j+1] = make_float4(0.f, 0.f, 0.f, 0.f); }

        const size_t o = (size_t)t * N4 + (size_t)j * 4 * BATCH_F4;
        const float4 s0 = lif4(mc[2*j],   er[s][0], vr[s][0], alpha, bw, cnt);
        const float4 s1 = lif4(mc[2*j+1], er[s][1], vr[s][1], alpha, bw, cnt);
        __stcs(out4 + o, s0);
        __stcs(out4 + o + 2 * BATCH_F4, s1);

        // Step boundary: reduce channel spike count, update bw. Next step's
        // first loads are already in flight.
        if (j == 7 && t < T_STEPS - 1) {
            float r = cnt;                     // integer-valued: exact any order
            #pragma unroll
            for (int off = 16; off > 0; off >>= 1)
                r += __shfl_down_sync(0xFFFFFFFFu, r, off);
            if (lane == 0) s_wsum[wid] = r;
            __syncthreads();
            if (wid == 0) {
                float x = (lane < NWARP) ? s_wsum[lane] : 0.0f;
                #pragma unroll
                for (int off = 8; off > 0; off >>= 1)
                    x += __shfl_down_sync(0xFFFFFFFFu, x, off);
                if (lane == 0) {
                    ema = 0.9f * ema + 0.1f * (x * INV_N);
                    const float inhw =
                        4.0f * (sigmoidf(LOWER_C - ema) - sigmoidf(ema - UPPER_C));
                    s_bw = beta * (1.0f - inhw);
                }
            }
            __syncthreads();
            bw  = s_bw;
            cnt = 0.0f;
        }
    }
}

extern "C" void kernel_launch(void* const* d_in, const int* in_sizes, int n_in,
                              void* d_out, int out_size)
{
    const float* xe = (const float*)d_in[0];  // x_exc  [T,B,C,H,W]
    const float* xi = (const float*)d_in[1];  // x_inh  [T,B,C,H,W]
    const float* ar = (const float*)d_in[2];  // alpha_raw scalar
    const float* br = (const float*)d_in[3];  // beta_raw scalar
    float* out = (float*)d_out;               // spikes [T,B,C,H,W]

    lif_all<<<CC, NTHR>>>(xe, xi, ar, br, out);
}

// round 15
// speedup vs baseline: 1.1986x; 1.0098x over previous
#include <cuda_runtime.h>
#include <cstdint>

// Problem shape (fixed by the reference)
#define T_STEPS 5
#define BB 32
#define CC 128
#define HW 1024                    // 32*32
#define NPT (BB * CC * HW)         // 4,194,304 elements per timestep
#define N4  (NPT / 4)              // 1,048,576 float4 per timestep
#define NTHR 512                   // threads per CTA (one CTA per channel)
#define NWARP (NTHR / 32)          // 16
#define BATCH_F4 (CC * HW / 4)     // 32768 float4 per batch slice
#define KTOT (T_STEPS * 8)         // 40 flat iterations (8 per step)

static constexpr float V_TH    = 0.5f;
static constexpr float W_DEC   = 0.5f;
static constexpr float LOWER_C = 0.2f - 0.03f;   // 0.17
static constexpr float UPPER_C = 0.2f + 0.03f;   // 0.23
static constexpr float EMA0    = 0.17f;
static constexpr float INV_N   = 1.0f / 32768.0f; // 1/(B*H*W)

__device__ __forceinline__ float sigmoidf(float x) {
    return 1.0f / (1.0f + expf(-x));
}

// LIF update for one float4; returns spike vec, updates m in place, accumulates cnt.
__device__ __forceinline__ float4 lif4(float4& m, const float4 e, const float4 v,
                                       const float alpha, const float bw, float& cnt) {
    float4 s;
    m.x = W_DEC * m.x + e.x / (1.0f + alpha * v.x) - bw * v.x;
    s.x = (m.x >= V_TH) ? 1.0f : 0.0f;  m.x -= V_TH * s.x;
    m.y = W_DEC * m.y + e.y / (1.0f + alpha * v.y) - bw * v.y;
    s.y = (m.y >= V_TH) ? 1.0f : 0.0f;  m.y -= V_TH * s.y;
    m.z = W_DEC * m.z + e.z / (1.0f + alpha * v.z) - bw * v.z;
    s.z = (m.z >= V_TH) ? 1.0f : 0.0f;  m.z -= V_TH * s.z;
    m.w = W_DEC * m.w + e.w / (1.0f + alpha * v.w) - bw * v.w;
    s.w = (m.w >= V_TH) ? 1.0f : 0.0f;  m.w -= V_TH * s.w;
    cnt += s.x + s.y + s.z + s.w;
    return s;
}

// One CTA per channel (128 CTAs, each on its own SM). Whole recurrence is
// channel-local. 512 threads; each thread owns 64 elements -> membrane carry
// is 16 float4 in REGISTERS (no smem LDS/STS in the hot loop). Inputs stream
// through a 2-slot register ring (distance-1 prefetch) over a flat, fully
// unrolled 40-iteration stream that crosses step boundaries, so the EMA
// reduction window always has next-step loads in flight.
__global__ __launch_bounds__(NTHR, 1)
void lif_all(const float* __restrict__ xe,
             const float* __restrict__ xi,
             const float* __restrict__ alpha_raw,
             const float* __restrict__ beta_raw,
             float* __restrict__ out)
{
    __shared__ float s_wsum[NWARP];
    __shared__ float s_bw;

    const int c    = blockIdx.x;               // channel
    const int tid  = threadIdx.x;
    const int lane = tid & 31;
    const int wid  = tid >> 5;

    const float alpha = 4.0f * sigmoidf(__ldg(alpha_raw));
    const float beta  = sigmoidf(__ldg(beta_raw));

    // Thread base: batch (tid>>8)∈{0,1}, channel c, offset tid&255.
    // Iteration (t, j) element r∈{0,1}: addr = base + t*N4 + j*4*BATCH_F4 + r*2*BATCH_F4
    const int base4 = (tid >> 8) * BATCH_F4 + c * (HW / 4) + (tid & 255);

    const float4* xe4  = reinterpret_cast<const float4*>(xe)  + base4;
    const float4* xi4  = reinterpret_cast<const float4*>(xi)  + base4;
    float4*       out4 = reinterpret_cast<float4*>(out)       + base4;

    float4 mc[16];                             // membrane carry (registers)
    float4 er[2][2], vr[2][2];                 // 2-slot input ring

    float ema = EMA0;                          // maintained by (wid0,lane0) only
    float bw  = beta;                          // inhw starts at 0
    float cnt = 0.0f;

    // Prologue: loads for k=0
    er[0][0] = __ldcs(xe4);
    er[0][1] = __ldcs(xe4 + 2 * BATCH_F4);
    vr[0][0] = __ldcs(xi4);
    vr[0][1] = __ldcs(xi4 + 2 * BATCH_F4);

    #pragma unroll
    for (int k = 0; k < KTOT; ++k) {
        const int t = k >> 3;                  // step (compile-time)
        const int j = k & 7;                   // chunk within step
        const int s = k & 1;                   // ring slot

        // Prefetch next iteration (crosses step boundaries; inputs are
        // independent of bw)
        if (k + 1 < KTOT) {
            const int t1 = (k + 1) >> 3, j1 = (k + 1) & 7;
            const size_t o1 = (size_t)t1 * N4 + (size_t)j1 * 4 * BATCH_F4;
            er[s ^ 1][0] = __ldcs(xe4 + o1);
            er[s ^ 1][1] = __ldcs(xe4 + o1 + 2 * BATCH_F4);
            vr[s ^ 1][0] = __ldcs(xi4 + o1);
            vr[s ^ 1][1] = __ldcs(xi4 + o1 + 2 * BATCH_F4);
        }

        if (t == 0) { mc[2*j]   = make_float4(0.f, 0.f, 0.f, 0.f);
                      mc[2*j+1] = make_float4(0.f, 0.f, 0.f, 0.f); }

        const size_t o = (size_t)t * N4 + (size_t)j * 4 * BATCH_F4;
        const float4 s0 = lif4(mc[2*j],   er[s][0], vr[s][0], alpha, bw, cnt);
        const float4 s1 = lif4(mc[2*j+1], er[s][1], vr[s][1], alpha, bw, cnt);
        __stcs(out4 + o, s0);
        __stcs(out4 + o + 2 * BATCH_F4, s1);

        // Step boundary: reduce channel spike count, update bw. Next step's
        // first loads are already in flight.
        if (j == 7 && t < T_STEPS - 1) {
            float r = cnt;                     // integer-valued: exact any order
            #pragma unroll
            for (int off = 16; off > 0; off >>= 1)
                r += __shfl_down_sync(0xFFFFFFFFu, r, off);
            if (lane == 0) s_wsum[wid] = r;
            __syncthreads();
            if (wid == 0) {
                float x = (lane < NWARP) ? s_wsum[lane] : 0.0f;
                #pragma unroll
                for (int off = 8; off > 0; off >>= 1)
                    x += __shfl_down_sync(0xFFFFFFFFu, x, off);
                if (lane == 0) {
                    ema = 0.9f * ema + 0.1f * (x * INV_N);
                    const float inhw =
                        4.0f * (sigmoidf(LOWER_C - ema) - sigmoidf(ema - UPPER_C));
                    s_bw = beta * (1.0f - inhw);
                }
            }
            __syncthreads();
            bw  = s_bw;
            cnt = 0.0f;
        }
    }
}

extern "C" void kernel_launch(void* const* d_in, const int* in_sizes, int n_in,
                              void* d_out, int out_size)
{
    const float* xe = (const float*)d_in[0];  // x_exc  [T,B,C,H,W]
    const float* xi = (const float*)d_in[1];  // x_inh  [T,B,C,H,W]
    const float* ar = (const float*)d_in[2];  // alpha_raw scalar
    const float* br = (const float*)d_in[3];  // beta_raw scalar
    float* out = (float*)d_out;               // spikes [T,B,C,H,W]

    lif_all<<<CC, NTHR>>>(xe, xi, ar, br, out);
}

// round 16
// speedup vs baseline: 1.4118x; 1.1779x over previous
#include <cuda_runtime.h>
#include <cstdint>

// Problem shape (fixed by the reference)
#define T_STEPS 5
#define BB 32
#define CC 128
#define HW 1024                    // 32*32
#define NPT (BB * CC * HW)         // 4,194,304 elements per timestep
#define N4  (NPT / 4)              // 1,048,576 float4 per timestep
#define NTHR 1024                  // threads per CTA (one CTA per channel)
#define BATCH_F4 (CC * HW / 4)     // 32768 float4 per batch slice
#define JSTRIDE  (4 * BATCH_F4)    // 131072: float4 stride between j-iterations
#define SMEM_BYTES (BB * HW * sizeof(float))   // 131072 B membrane carry
#define KTOT (T_STEPS * 8)         // 40 flat iterations

static constexpr float V_TH    = 0.5f;
static constexpr float W_DEC   = 0.5f;
static constexpr float LOWER_C = 0.2f - 0.03f;   // 0.17
static constexpr float UPPER_C = 0.2f + 0.03f;   // 0.23
static constexpr float EMA0    = 0.17f;
static constexpr float INV_N   = 1.0f / 32768.0f; // 1/(B*H*W)

__device__ __forceinline__ float sigmoidf(float x) {
    return 1.0f / (1.0f + expf(-x));
}

// One CTA per channel; whole recurrence is channel-local (no cross-CTA comm).
// Flat 40-iteration stream (5 steps x 8 j), fully unrolled, 3-slot load ring
// carried ACROSS step boundaries (EMA window runs with loads in flight).
// Membrane carry in smem (thread-private slots). Division via __fdividef
// (RCP+mul): inputs are O(1), denom in [1,3), rel-err budget 1e-3.
__global__ __launch_bounds__(NTHR, 1)
void lif_all(const float* __restrict__ xe,
             const float* __restrict__ xi,
             const float* __restrict__ alpha_raw,
             const float* __restrict__ beta_raw,
             float* __restrict__ out)
{
    extern __shared__ float4 s_mem[];          // 131 KB membrane carry
    __shared__ float s_wsum[NTHR / 32];
    __shared__ float s_bw;

    const int c    = blockIdx.x;               // channel
    const int tid  = threadIdx.x;
    const int lane = tid & 31;
    const int wid  = tid >> 5;

    const float alpha = 4.0f * sigmoidf(__ldg(alpha_raw));
    const float beta  = sigmoidf(__ldg(beta_raw));

    // Thread's base float4 index for j=0: batch (tid>>8), channel c, offset tid&255
    const int g0 = (tid >> 8) * BATCH_F4 + c * (HW / 4) + (tid & 255);

    const float4* xe4  = reinterpret_cast<const float4*>(xe) + g0;
    const float4* xi4  = reinterpret_cast<const float4*>(xi) + g0;
    float4*       out4 = reinterpret_cast<float4*>(out)      + g0;

    float ema = EMA0;                          // maintained by (wid0,lane0) only
    float bw  = beta;                          // inhw starts at 0
    float4 cnt4 = make_float4(0.f, 0.f, 0.f, 0.f);

    float4 er[3], vr[3];
    // Prologue: loads for k=0,1
    er[0] = __ldcs(xe4);                 vr[0] = __ldcs(xi4);
    er[1] = __ldcs(xe4 + JSTRIDE);       vr[1] = __ldcs(xi4 + JSTRIDE);

    #pragma unroll
    for (int k = 0; k < KTOT; ++k) {
        const int t = k >> 3;                  // step (compile-time)
        const int j = k & 7;                   // plane-group within step

        // Issue loads two iterations ahead (crosses step boundaries)
        if (k + 2 < KTOT) {
            const int t2 = (k + 2) >> 3, j2 = (k + 2) & 7;
            const size_t off = (size_t)t2 * N4 + (size_t)j2 * JSTRIDE;
            er[(k + 2) % 3] = __ldcs(xe4 + off);
            vr[(k + 2) % 3] = __ldcs(xi4 + off);
        }

        const float4 e = er[k % 3];
        const float4 v = vr[k % 3];
        float4 m = (t == 0) ? make_float4(0.f, 0.f, 0.f, 0.f)
                            : s_mem[j * NTHR + tid];
        float4 s;

        m.x = W_DEC * m.x + __fdividef(e.x, 1.0f + alpha * v.x) - bw * v.x;
        s.x = (m.x >= V_TH) ? 1.0f : 0.0f;  m.x -= V_TH * s.x;
        m.y = W_DEC * m.y + __fdividef(e.y, 1.0f + alpha * v.y) - bw * v.y;
        s.y = (m.y >= V_TH) ? 1.0f : 0.0f;  m.y -= V_TH * s.y;
        m.z = W_DEC * m.z + __fdividef(e.z, 1.0f + alpha * v.z) - bw * v.z;
        s.z = (m.z >= V_TH) ? 1.0f : 0.0f;  m.z -= V_TH * s.z;
        m.w = W_DEC * m.w + __fdividef(e.w, 1.0f + alpha * v.w) - bw * v.w;
        s.w = (m.w >= V_TH) ? 1.0f : 0.0f;  m.w -= V_TH * s.w;

        __stcs(out4 + (size_t)t * N4 + (size_t)j * JSTRIDE, s);

        if (t < T_STEPS - 1) {
            s_mem[j * NTHR + tid] = m;
            cnt4.x += s.x;  cnt4.y += s.y;     // 4 independent accumulators
            cnt4.z += s.z;  cnt4.w += s.w;
        }

        // Step boundary: reduce this channel's spike count, update bw.
        // Next step's first loads are ALREADY in flight (issued at k-1, k).
        if (j == 7 && t < T_STEPS - 1) {
            float r = (cnt4.x + cnt4.y) + (cnt4.z + cnt4.w);  // exact: integers
            #pragma unroll
            for (int off = 16; off > 0; off >>= 1)
                r += __shfl_down_sync(0xFFFFFFFFu, r, off);
            if (lane == 0) s_wsum[wid] = r;
            __syncthreads();
            if (wid == 0) {
                float x = s_wsum[lane];        // exactly 32 warps
                #pragma unroll
                for (int off = 16; off > 0; off >>= 1)
                    x += __shfl_down_sync(0xFFFFFFFFu, x, off);
                if (lane == 0) {
                    ema = 0.9f * ema + 0.1f * (x * INV_N);
                    const float inhw =
                        4.0f * (sigmoidf(LOWER_C - ema) - sigmoidf(ema - UPPER_C));
                    s_bw = beta * (1.0f - inhw);
                }
            }
            __syncthreads();
            bw   = s_bw;
            cnt4 = make_float4(0.f, 0.f, 0.f, 0.f);
        }
    }
}

extern "C" void kernel_launch(void* const* d_in, const int* in_sizes, int n_in,
                              void* d_out, int out_size)
{
    const float* xe = (const float*)d_in[0];  // x_exc  [T,B,C,H,W]
    const float* xi = (const float*)d_in[1];  // x_inh  [T,B,C,H,W]
    const float* ar = (const float*)d_in[2];  // alpha_raw scalar
    const float* br = (const float*)d_in[3];  // beta_raw scalar
    float* out = (float*)d_out;               // spikes [T,B,C,H,W]

    static bool attr_set = false;
    if (!attr_set) {
        cudaFuncSetAttribute(lif_all, cudaFuncAttributeMaxDynamicSharedMemorySize,
                             SMEM_BYTES);
        attr_set = true;
    }
    lif_all<<<CC, NTHR, SMEM_BYTES>>>(xe, xi, ar, br, out);
}

// round 17
// speedup vs baseline: 1.4205x; 1.0062x over previous
#include <cuda_runtime.h>
#include <cstdint>

// Problem shape (fixed by the reference)
#define T_STEPS 5
#define BB 32
#define CC 128
#define HW 1024                    // 32*32
#define NPT (BB * CC * HW)         // 4,194,304 elements per timestep
#define N4  (NPT / 4)              // 1,048,576 float4 per timestep
#define NTHR 1024                  // threads per CTA (one CTA per channel)
#define BATCH_F4 (CC * HW / 4)     // 32768 float4 per batch slice
#define JSTRIDE  (4 * BATCH_F4)    // 131072: float4 stride between j-iterations
#define SMEM_BYTES (BB * HW * sizeof(float))   // 131072 B membrane carry
#define KTOT (T_STEPS * 8)         // 40 flat iterations
#define PF_DIST 4                  // L2-prefetch distance (iterations)

static constexpr float V_TH    = 0.5f;
static constexpr float W_DEC   = 0.5f;
static constexpr float LOWER_C = 0.2f - 0.03f;   // 0.17
static constexpr float UPPER_C = 0.2f + 0.03f;   // 0.23
static constexpr float EMA0    = 0.17f;
static constexpr float INV_N   = 1.0f / 32768.0f; // 1/(B*H*W)

__device__ __forceinline__ float sigmoidf(float x) {
    return 1.0f / (1.0f + expf(-x));
}

__device__ __forceinline__ void prefetch_l2(const void* p) {
    asm volatile("prefetch.global.L2 [%0];" :: "l"(p));
}

// One CTA per channel; whole recurrence is channel-local (no cross-CTA comm).
// Flat 40-iteration stream (5 steps x 8 j), fully unrolled:
//   - L2 prefetch at distance 4 (register-free deep pipeline stage)
//   - 3-slot register ring (__ldcs) at distance 2 -> now hits L2, not DRAM
//   - membrane carry in smem (thread-private slots)
//   - ring carried ACROSS step boundaries (EMA window has loads in flight)
__global__ __launch_bounds__(NTHR, 1)
void lif_all(const float* __restrict__ xe,
             const float* __restrict__ xi,
             const float* __restrict__ alpha_raw,
             const float* __restrict__ beta_raw,
             float* __restrict__ out)
{
    extern __shared__ float4 s_mem[];          // 131 KB membrane carry
    __shared__ float s_wsum[NTHR / 32];
    __shared__ float s_bw;

    const int c    = blockIdx.x;               // channel
    const int tid  = threadIdx.x;
    const int lane = tid & 31;
    const int wid  = tid >> 5;

    const float alpha = 4.0f * sigmoidf(__ldg(alpha_raw));
    const float beta  = sigmoidf(__ldg(beta_raw));

    // Thread's base float4 index for j=0: batch (tid>>8), channel c, offset tid&255
    const int g0 = (tid >> 8) * BATCH_F4 + c * (HW / 4) + (tid & 255);

    const float4* xe4  = reinterpret_cast<const float4*>(xe) + g0;
    const float4* xi4  = reinterpret_cast<const float4*>(xi) + g0;
    float4*       out4 = reinterpret_cast<float4*>(out)      + g0;

    float ema = EMA0;                          // maintained by (wid0,lane0) only
    float bw  = beta;                          // inhw starts at 0
    float4 cnt4 = make_float4(0.f, 0.f, 0.f, 0.f);
    const bool pf_lane = ((lane & 7) == 0);    // one prefetch per 128B line

    float4 er[3], vr[3];
    // Prologue: L2 prefetch for k=2..PF_DIST-1 window, ring loads for k=0,1
    #pragma unroll
    for (int k0 = 2; k0 < PF_DIST; ++k0) {
        const size_t off = (size_t)(k0 >> 3) * N4 + (size_t)(k0 & 7) * JSTRIDE;
        if (pf_lane) { prefetch_l2(xe4 + off); prefetch_l2(xi4 + off); }
    }
    er[0] = __ldcs(xe4);                 vr[0] = __ldcs(xi4);
    er[1] = __ldcs(xe4 + JSTRIDE);       vr[1] = __ldcs(xi4 + JSTRIDE);

    #pragma unroll
    for (int k = 0; k < KTOT; ++k) {
        const int t = k >> 3;                  // step (compile-time)
        const int j = k & 7;                   // plane-group within step

        // Deep stage: L2 prefetch at distance PF_DIST (no registers consumed)
        if (k + PF_DIST < KTOT) {
            const int tp = (k + PF_DIST) >> 3, jp = (k + PF_DIST) & 7;
            const size_t offp = (size_t)tp * N4 + (size_t)jp * JSTRIDE;
            if (pf_lane) { prefetch_l2(xe4 + offp); prefetch_l2(xi4 + offp); }
        }

        // Near stage: ring loads at distance 2 (crosses step boundaries)
        if (k + 2 < KTOT) {
            const int t2 = (k + 2) >> 3, j2 = (k + 2) & 7;
            const size_t off = (size_t)t2 * N4 + (size_t)j2 * JSTRIDE;
            er[(k + 2) % 3] = __ldcs(xe4 + off);
            vr[(k + 2) % 3] = __ldcs(xi4 + off);
        }

        const float4 e = er[k % 3];
        const float4 v = vr[k % 3];
        float4 m = (t == 0) ? make_float4(0.f, 0.f, 0.f, 0.f)
                            : s_mem[j * NTHR + tid];
        float4 s;

        m.x = W_DEC * m.x + __fdividef(e.x, 1.0f + alpha * v.x) - bw * v.x;
        s.x = (m.x >= V_TH) ? 1.0f : 0.0f;  m.x -= V_TH * s.x;
        m.y = W_DEC * m.y + __fdividef(e.y, 1.0f + alpha * v.y) - bw * v.y;
        s.y = (m.y >= V_TH) ? 1.0f : 0.0f;  m.y -= V_TH * s.y;
        m.z = W_DEC * m.z + __fdividef(e.z, 1.0f + alpha * v.z) - bw * v.z;
        s.z = (m.z >= V_TH) ? 1.0f : 0.0f;  m.z -= V_TH * s.z;
        m.w = W_DEC * m.w + __fdividef(e.w, 1.0f + alpha * v.w) - bw * v.w;
        s.w = (m.w >= V_TH) ? 1.0f : 0.0f;  m.w -= V_TH * s.w;

        __stcs(out4 + (size_t)t * N4 + (size_t)j * JSTRIDE, s);

        if (t < T_STEPS - 1) {
            s_mem[j * NTHR + tid] = m;
            cnt4.x += s.x;  cnt4.y += s.y;     // 4 independent accumulators
            cnt4.z += s.z;  cnt4.w += s.w;
        }

        // Step boundary: reduce this channel's spike count, update bw.
        // Next step's loads/prefetches are ALREADY in flight.
        if (j == 7 && t < T_STEPS - 1) {
            float r = (cnt4.x + cnt4.y) + (cnt4.z + cnt4.w);  // exact: integers
            #pragma unroll
            for (int off = 16; off > 0; off >>= 1)
                r += __shfl_down_sync(0xFFFFFFFFu, r, off);
            if (lane == 0) s_wsum[wid] = r;
            __syncthreads();
            if (wid == 0) {
                float x = s_wsum[lane];        // exactly 32 warps
                #pragma unroll
                for (int off = 16; off > 0; off >>= 1)
                    x += __shfl_down_sync(0xFFFFFFFFu, x, off);
                if (lane == 0) {
                    ema = 0.9f * ema + 0.1f * (x * INV_N);
                    const float inhw =
                        4.0f * (sigmoidf(LOWER_C - ema) - sigmoidf(ema - UPPER_C));
                    s_bw = beta * (1.0f - inhw);
                }
            }
            __syncthreads();
            bw   = s_bw;
            cnt4 = make_float4(0.f, 0.f, 0.f, 0.f);
        }
    }
}

extern "C" void kernel_launch(void* const* d_in, const int* in_sizes, int n_in,
                              void* d_out, int out_size)
{
    const float* xe = (const float*)d_in[0];  // x_exc  [T,B,C,H,W]
    const float* xi = (const float*)d_in[1];  // x_inh  [T,B,C,H,W]
    const float* ar = (const float*)d_in[2];  // alpha_raw scalar
    const float* br = (const float*)d_in[3];  // beta_raw scalar
    float* out = (float*)d_out;               // spikes [T,B,C,H,W]

    static bool attr_set = false;
    if (!attr_set) {
        cudaFuncSetAttribute(lif_all, cudaFuncAttributeMaxDynamicSharedMemorySize,
                             SMEM_BYTES);
        attr_set = true;
    }
    lif_all<<<CC, NTHR, SMEM_BYTES>>>(xe, xi, ar, br, out);
}